// round 3
// baseline (speedup 1.0000x reference)
#include <cuda_runtime.h>
#include <cuda_bf16.h>
#include <cstdint>
#include <cstddef>

#define BATCH 8
#define TLEN  4096
#define PDIM  1024
#define RDIM  128
#define MROWS (BATCH*TLEN)
#define SCALE 0.08838834764831845f
#define EPS_V 1e-6f

// scratch (device globals; no allocation allowed)
__device__ float g_r[(size_t)MROWS * RDIM];
__device__ float g_u[(size_t)MROWS * RDIM];
__device__ float g_a[(size_t)MROWS * RDIM];
__device__ float g_s[(size_t)MROWS * RDIM];

__device__ __forceinline__ unsigned f2tf(float x) {
    unsigned r; asm("cvt.rna.tf32.f32 %0, %1;" : "=r"(r) : "f"(x)); return r;
}
__device__ __forceinline__ void mma_tf32(float* c, const unsigned* a, const unsigned* b) {
    asm volatile(
        "mma.sync.aligned.m16n8k8.row.col.f32.tf32.tf32.f32 "
        "{%0,%1,%2,%3},{%4,%5,%6,%7},{%8,%9},{%0,%1,%2,%3};"
        : "+f"(c[0]), "+f"(c[1]), "+f"(c[2]), "+f"(c[3])
        : "r"(a[0]), "r"(a[1]), "r"(a[2]), "r"(a[3]), "r"(b[0]), "r"(b[1]));
}

#define BM 128
#define BN 128
#define BK 32
#define ASTRIDE 36
#define BSTRIDE 136
#define ASTG (BM * ASTRIDE)
#define BSTG (BK * BSTRIDE)

// MODE 0: C = A@B    MODE 1: C = (A.*A2*SCALE)@B
// MODE 2: C = clip(sigmoid(A@B + bias))    MODE 3: C = A@B + X
template <int MODE>
__global__ void __launch_bounds__(256, 1)
gemm_tf32(const float* __restrict__ A, const float* __restrict__ A2,
          const float* __restrict__ Bm, const float* __restrict__ X,
          float* __restrict__ C, int K, int lda, int ldb, int ldc) {
    __shared__ unsigned As[ASTG];
    __shared__ unsigned Bs[BSTG];

    const int tid  = threadIdx.x;
    const int wid  = tid >> 5;
    const int lane = tid & 31;
    const int grp  = lane >> 2;
    const int qid  = lane & 3;
    const int wm   = (wid & 3) * 32;
    const int wn   = (wid >> 2) * 64;
    const size_t m0 = (size_t)blockIdx.x * BM;
    const int    n0 = blockIdx.y * BN;

    float acc[2][8][4];
#pragma unroll
    for (int mt = 0; mt < 2; mt++)
#pragma unroll
        for (int nt = 0; nt < 8; nt++)
#pragma unroll
            for (int i = 0; i < 4; i++) acc[mt][nt][i] = 0.0f;

    const int NK = K / BK;
    float4 ra[4], rf[4], rb[4];

    int aRow[4], aC4[4], bK[4], bN[4];
#pragma unroll
    for (int i = 0; i < 4; i++) {
        int idx = tid + i * 256;
        aRow[i] = idx >> 3;  aC4[i] = (idx & 7) << 2;
        bK[i]   = idx >> 5;  bN[i]  = (idx & 31) << 2;
    }

    auto ldg = [&](int kc) {
#pragma unroll
        for (int i = 0; i < 4; i++) {
            size_t aoff = (m0 + aRow[i]) * (size_t)lda + kc * BK + aC4[i];
            ra[i] = *(const float4*)(A + aoff);
            if (MODE == 1) rf[i] = *(const float4*)(A2 + aoff);
            size_t boff = (size_t)(kc * BK + bK[i]) * (size_t)ldb + n0 + bN[i];
            rb[i] = *(const float4*)(Bm + boff);
        }
    };
    auto sts = [&]() {
#pragma unroll
        for (int i = 0; i < 4; i++) {
            float4 v = ra[i];
            if (MODE == 1) {
                v.x *= rf[i].x * SCALE; v.y *= rf[i].y * SCALE;
                v.z *= rf[i].z * SCALE; v.w *= rf[i].w * SCALE;
            }
            *(uint4*)&As[aRow[i] * ASTRIDE + aC4[i]] =
                make_uint4(f2tf(v.x), f2tf(v.y), f2tf(v.z), f2tf(v.w));
            float4 w = rb[i];
            *(uint4*)&Bs[bK[i] * BSTRIDE + bN[i]] =
                make_uint4(f2tf(w.x), f2tf(w.y), f2tf(w.z), f2tf(w.w));
        }
    };
    auto compute = [&]() {
        const unsigned* Ab = As + wm * ASTRIDE;
        const unsigned* Bb = Bs + wn;
#pragma unroll
        for (int ks = 0; ks < 4; ks++) {
            const int k = ks * 8;
            unsigned af[2][4];
#pragma unroll
            for (int mt = 0; mt < 2; mt++) {
                const unsigned* p = Ab + (mt * 16 + grp) * ASTRIDE + k + qid;
                af[mt][0] = p[0];
                af[mt][1] = p[8 * ASTRIDE];
                af[mt][2] = p[4];
                af[mt][3] = p[8 * ASTRIDE + 4];
            }
            unsigned bf[8][2];
#pragma unroll
            for (int nt = 0; nt < 8; nt++) {
                const unsigned* p = Bb + (k + qid) * BSTRIDE + nt * 8 + grp;
                bf[nt][0] = p[0];
                bf[nt][1] = p[4 * BSTRIDE];
            }
#pragma unroll
            for (int mt = 0; mt < 2; mt++)
#pragma unroll
                for (int nt = 0; nt < 8; nt++)
                    mma_tf32(acc[mt][nt], af[mt], bf[nt]);
        }
    };

    ldg(0);
    sts();
    __syncthreads();
    for (int kc = 0; kc < NK; ++kc) {
        if (kc + 1 < NK) ldg(kc + 1);
        compute();
        __syncthreads();
        if (kc + 1 < NK) { sts(); __syncthreads(); }
    }

#pragma unroll
    for (int mt = 0; mt < 2; mt++) {
#pragma unroll
        for (int nt = 0; nt < 8; nt++) {
            int row = wm + mt * 16 + grp;
            int col = wn + nt * 8 + 2 * qid;
            size_t g0 = (m0 + row) * (size_t)ldc + n0 + col;
            size_t g2 = (m0 + row + 8) * (size_t)ldc + n0 + col;
            float v0 = acc[mt][nt][0], v1 = acc[mt][nt][1];
            float v2 = acc[mt][nt][2], v3 = acc[mt][nt][3];
            if (MODE == 2) {
                float b0 = X[n0 + col], b1 = X[n0 + col + 1];
                v0 = 1.0f / (1.0f + __expf(-(v0 + b0)));
                v1 = 1.0f / (1.0f + __expf(-(v1 + b1)));
                v2 = 1.0f / (1.0f + __expf(-(v2 + b0)));
                v3 = 1.0f / (1.0f + __expf(-(v3 + b1)));
                v0 = fminf(fmaxf(v0, 0.01f), 0.995f);
                v1 = fminf(fmaxf(v1, 0.01f), 0.995f);
                v2 = fminf(fmaxf(v2, 0.01f), 0.995f);
                v3 = fminf(fmaxf(v3, 0.01f), 0.995f);
            } else if (MODE == 3) {
                float2 r0 = *(const float2*)(X + g0);
                float2 r2 = *(const float2*)(X + g2);
                v0 += r0.x; v1 += r0.y; v2 += r2.x; v3 += r2.y;
            }
            *(float2*)(C + g0) = make_float2(v0, v1);
            *(float2*)(C + g2) = make_float2(v2, v3);
        }
    }
}

// -------- sequential normalized scan: 4 blocks x 32 threads, 2 batches/warp --------
__device__ __forceinline__ float4 f4mul(float4 a, float4 b) {
    return make_float4(a.x*b.x, a.y*b.y, a.z*b.z, a.w*b.w);
}
__device__ __forceinline__ float4 f4fms(float4 p, float s, float4 u) {
    return make_float4(fmaf(p.x,s,u.x), fmaf(p.y,s,u.y), fmaf(p.z,s,u.z), fmaf(p.w,s,u.w));
}
__device__ __forceinline__ float4 f4sc(float4 a, float s) {
    return make_float4(a.x*s, a.y*s, a.z*s, a.w*s);
}
__device__ __forceinline__ float f4ssq(float4 a) {
    return fmaf(a.x,a.x, a.y*a.y) + fmaf(a.z,a.z, a.w*a.w);
}

__global__ void scan_kernel(const float* __restrict__ A, const float* __restrict__ U,
                            float* __restrict__ S, float* __restrict__ cache) {
    const int lane = threadIdx.x & 31;
    const int b    = blockIdx.x * 2 + (lane >> 4);
    const int li   = lane & 15;
    const size_t base = ((size_t)b * TLEN) * RDIM + li * 8;
    const float4* Ap = (const float4*)(A + base);
    const float4* Up = (const float4*)(U + base);
    float4*       Sp = (float4*)(S + base);

    float4 w0 = Up[0], w1 = Up[1];               // w_0 = u_0
    float4 aN0 = Ap[32], aN1 = Ap[33];           // step 1
    float4 uN0 = Up[32], uN1 = Up[33];
    float4 aM0 = Ap[64], aM1 = Ap[65];           // step 2
    float4 uM0 = Up[64], uM1 = Up[65];

    for (int t = 0; t < TLEN; ++t) {
        // off-critical-path: p = a_{t+1} .* w_t
        float4 p0 = f4mul(aN0, w0);
        float4 p1 = f4mul(aN1, w1);
        // sum of squares of w_t
        float q = f4ssq(w0) + f4ssq(w1);
        q += __shfl_xor_sync(0xffffffffu, q, 1);
        q += __shfl_xor_sync(0xffffffffu, q, 2);
        q += __shfl_xor_sync(0xffffffffu, q, 4);
        q += __shfl_xor_sync(0xffffffffu, q, 8);
        float inv = rsqrtf(fmaf(q, 1.0f / 128.0f, EPS_V));
        // s_t = w_t * inv
        float4 s0 = f4sc(w0, inv);
        float4 s1 = f4sc(w1, inv);
        size_t so = (size_t)t * 32;
        Sp[so]     = s0;
        Sp[so + 1] = s1;
        if (t == TLEN - 1) {
            *(float4*)(cache + b * RDIM + li * 8)     = s0;
            *(float4*)(cache + b * RDIM + li * 8 + 4) = s1;
        }
        // w_{t+1} = p * inv + u_{t+1}   (single FMA after rsqrt)
        w0 = f4fms(p0, inv, uN0);
        w1 = f4fms(p1, inv, uN1);
        // rotate prefetch pipeline
        aN0 = aM0; aN1 = aM1; uN0 = uM0; uN1 = uM1;
        if (t + 3 < TLEN) {
            size_t o = (size_t)(t + 3) * 32;
            aM0 = Ap[o]; aM1 = Ap[o + 1];
            uM0 = Up[o]; uM1 = Up[o + 1];
        }
    }
}

extern "C" void kernel_launch(void* const* d_in, const int* in_sizes, int n_in,
                              void* d_out, int out_size) {
    const float* t_in = (const float*)d_in[0];
    const float* F_in = (const float*)d_in[1];
    const float* V_r  = (const float*)d_in[2];
    const float* V_b  = (const float*)d_in[3];
    const float* V_o  = (const float*)d_in[4];
    const float* W_l  = (const float*)d_in[5];
    const float* b_l  = (const float*)d_in[6];
    float* out = (float*)d_out;

    float *r, *u, *a, *s;
    cudaGetSymbolAddress((void**)&r, g_r);
    cudaGetSymbolAddress((void**)&u, g_u);
    cudaGetSymbolAddress((void**)&a, g_a);
    cudaGetSymbolAddress((void**)&s, g_s);

    dim3 blk(256);
    dim3 grd1(MROWS / BM, 1);
    dim3 grd8(MROWS / BM, PDIM / BN);

    // r = t @ V_r
    gemm_tf32<0><<<grd1, blk>>>(t_in, nullptr, V_r, nullptr, r, PDIM, PDIM, RDIM, RDIM);
    // u = (F .* t) @ V_b * scale
    gemm_tf32<1><<<grd1, blk>>>(t_in, F_in, V_b, nullptr, u, PDIM, PDIM, RDIM, RDIM);
    // a = clip(sigmoid(r @ W_lambda + b_lambda))
    gemm_tf32<2><<<grd1, blk>>>(r, nullptr, W_l, b_l, a, RDIM, RDIM, RDIM, RDIM);
    // sequential normalized scan (+ writes new_cache tail of d_out)
    float* cache = out + (size_t)MROWS * PDIM;
    scan_kernel<<<4, 32>>>(a, u, s, cache);
    // t_tilde = s @ V_o + t
    gemm_tf32<3><<<grd8, blk>>>(s, nullptr, V_o, t_in, out, RDIM, RDIM, PDIM, PDIM);
}

// round 4
// speedup vs baseline: 2.9599x; 2.9599x over previous
#include <cuda_runtime.h>
#include <cuda_bf16.h>
#include <cstdint>
#include <cstddef>

#define BATCH 8
#define TLEN  4096
#define PDIM  1024
#define RDIM  128
#define MROWS (BATCH*TLEN)
#define SCALE 0.08838834764831845f
#define EPS_V 1e-6f

// scratch (device globals; no allocation allowed)
__device__ float g_u[(size_t)MROWS * RDIM];
__device__ float g_a[(size_t)MROWS * RDIM];
__device__ float g_s[(size_t)MROWS * RDIM];

__device__ __forceinline__ unsigned f2tf(float x) {
    unsigned r; asm("cvt.rna.tf32.f32 %0, %1;" : "=r"(r) : "f"(x)); return r;
}
__device__ __forceinline__ void mma_tf32(float* c, const unsigned* a, const unsigned* b) {
    asm volatile(
        "mma.sync.aligned.m16n8k8.row.col.f32.tf32.tf32.f32 "
        "{%0,%1,%2,%3},{%4,%5,%6,%7},{%8,%9},{%0,%1,%2,%3};"
        : "+f"(c[0]), "+f"(c[1]), "+f"(c[2]), "+f"(c[3])
        : "r"(a[0]), "r"(a[1]), "r"(a[2]), "r"(a[3]), "r"(b[0]), "r"(b[1]));
}

#define BM 128
#define BN 128
#define BK 32
#define ASTRIDE 36
#define BSTRIDE 136
#define ASTG (BM * ASTRIDE)            // 4608 words
#define BSTG (BK * BSTRIDE)            // 4352 words
#define STGW (ASTG + BSTG)             // 8960 words per stage
#define RS   132                        // phase-2 smem stride
#define SMEM_WORDS_STD   (2 * STGW)                 // 17920
#define SMEM_WORDS_FUSED (2 * 128 * RS)             // 33792 (r_s + W_s)
#define SMEM_BYTES_STD   (SMEM_WORDS_STD * 4)       // 71680
#define SMEM_BYTES_FUSED (SMEM_WORDS_FUSED * 4)     // 135168

// MODE 0: phase1 r = A@Bm kept in-CTA; phase2 a = clip(sigmoid(r @ W + bias)) -> C
// MODE 1: C = (A .* A2 * SCALE) @ Bm
// MODE 3: C = A @ Bm + X
template <int MODE>
__global__ void __launch_bounds__(256)
gk(const float* __restrict__ A, const float* __restrict__ A2,
   const float* __restrict__ Bm, const float* __restrict__ W,
   const float* __restrict__ bias, const float* __restrict__ X,
   float* __restrict__ C, int K, int lda, int ldb, int ldc) {
    extern __shared__ unsigned sm[];

    const int tid  = threadIdx.x;
    const int wid  = tid >> 5;
    const int lane = tid & 31;
    const int grp  = lane >> 2;
    const int qid  = lane & 3;
    const int wm   = (wid & 3) * 32;
    const int wn   = (wid >> 2) * 64;
    const size_t m0 = (size_t)blockIdx.x * BM;
    const int    n0 = blockIdx.y * BN;

    float acc[2][8][4];
#pragma unroll
    for (int mt = 0; mt < 2; mt++)
#pragma unroll
        for (int nt = 0; nt < 8; nt++)
#pragma unroll
            for (int i = 0; i < 4; i++) acc[mt][nt][i] = 0.0f;

    const int NK = K / BK;
    float4 ra[4], rf[4], rb[4];

    int aRow[4], aC4[4], bK[4], bN[4];
#pragma unroll
    for (int i = 0; i < 4; i++) {
        int idx = tid + i * 256;
        aRow[i] = idx >> 3;  aC4[i] = (idx & 7) << 2;
        bK[i]   = idx >> 5;  bN[i]  = (idx & 31) << 2;
    }

    auto ldg = [&](int kc) {
#pragma unroll
        for (int i = 0; i < 4; i++) {
            size_t aoff = (m0 + aRow[i]) * (size_t)lda + kc * BK + aC4[i];
            ra[i] = *(const float4*)(A + aoff);
            if (MODE == 1) rf[i] = *(const float4*)(A2 + aoff);
            size_t boff = (size_t)(kc * BK + bK[i]) * (size_t)ldb + n0 + bN[i];
            rb[i] = *(const float4*)(Bm + boff);
        }
    };
    auto sts = [&](int stg) {
        unsigned* As = sm + stg * STGW;
        unsigned* Bs = As + ASTG;
#pragma unroll
        for (int i = 0; i < 4; i++) {
            float4 v = ra[i];
            if (MODE == 1) {
                v.x *= rf[i].x * SCALE; v.y *= rf[i].y * SCALE;
                v.z *= rf[i].z * SCALE; v.w *= rf[i].w * SCALE;
            }
            *(uint4*)&As[aRow[i] * ASTRIDE + aC4[i]] =
                make_uint4(f2tf(v.x), f2tf(v.y), f2tf(v.z), f2tf(v.w));
            float4 w = rb[i];
            *(uint4*)&Bs[bK[i] * BSTRIDE + bN[i]] =
                make_uint4(f2tf(w.x), f2tf(w.y), f2tf(w.z), f2tf(w.w));
        }
    };
    auto compute = [&](int stg) {
        const unsigned* Ab = sm + stg * STGW + wm * ASTRIDE;
        const unsigned* Bb = sm + stg * STGW + ASTG + wn;
#pragma unroll
        for (int ks = 0; ks < 4; ks++) {
            const int k = ks * 8;
            unsigned af[2][4];
#pragma unroll
            for (int mt = 0; mt < 2; mt++) {
                const unsigned* p = Ab + (mt * 16 + grp) * ASTRIDE + k + qid;
                af[mt][0] = p[0];
                af[mt][1] = p[8 * ASTRIDE];
                af[mt][2] = p[4];
                af[mt][3] = p[8 * ASTRIDE + 4];
            }
            unsigned bf[8][2];
#pragma unroll
            for (int nt = 0; nt < 8; nt++) {
                const unsigned* p = Bb + (k + qid) * BSTRIDE + nt * 8 + grp;
                bf[nt][0] = p[0];
                bf[nt][1] = p[4 * BSTRIDE];
            }
#pragma unroll
            for (int mt = 0; mt < 2; mt++)
#pragma unroll
                for (int nt = 0; nt < 8; nt++)
                    mma_tf32(acc[mt][nt], af[mt], bf[nt]);
        }
    };

    // 2-stage pipeline, one sync per iteration
    ldg(0);
    sts(0);
    __syncthreads();
    for (int kc = 0; kc < NK; ++kc) {
        int cur = kc & 1;
        if (kc + 1 < NK) ldg(kc + 1);
        compute(cur);
        if (kc + 1 < NK) sts(cur ^ 1);
        __syncthreads();
    }

    if (MODE == 0) {
        // ---- fused phase 2: a = clip(sigmoid(r @ W + bias)) ----
        unsigned* r_s = sm;             // 128 x RS
        unsigned* W_s = sm + 128 * RS;  // 128 x RS
        // write r tile (tf32) to smem
#pragma unroll
        for (int mt = 0; mt < 2; mt++) {
#pragma unroll
            for (int nt = 0; nt < 8; nt++) {
                int row = wm + mt * 16 + grp;
                int col = wn + nt * 8 + 2 * qid;
                r_s[row * RS + col]           = f2tf(acc[mt][nt][0]);
                r_s[row * RS + col + 1]       = f2tf(acc[mt][nt][1]);
                r_s[(row + 8) * RS + col]     = f2tf(acc[mt][nt][2]);
                r_s[(row + 8) * RS + col + 1] = f2tf(acc[mt][nt][3]);
            }
        }
        // load W (128x128) into smem as tf32
#pragma unroll
        for (int i = 0; i < 16; i++) {
            int idx = tid + i * 256;          // 4096 float4
            int row = idx >> 5;
            int c4  = (idx & 31) << 2;
            float4 v = *(const float4*)(W + row * RDIM + c4);
            *(uint4*)&W_s[row * RS + c4] =
                make_uint4(f2tf(v.x), f2tf(v.y), f2tf(v.z), f2tf(v.w));
        }
        __syncthreads();

        float acc2[2][8][4];
#pragma unroll
        for (int mt = 0; mt < 2; mt++)
#pragma unroll
            for (int nt = 0; nt < 8; nt++)
#pragma unroll
                for (int i = 0; i < 4; i++) acc2[mt][nt][i] = 0.0f;

#pragma unroll
        for (int ks = 0; ks < 16; ks++) {
            const int k = ks * 8;
            unsigned af[2][4];
#pragma unroll
            for (int mt = 0; mt < 2; mt++) {
                const unsigned* p = r_s + (wm + mt * 16 + grp) * RS + k + qid;
                af[mt][0] = p[0];
                af[mt][1] = p[8 * RS];
                af[mt][2] = p[4];
                af[mt][3] = p[8 * RS + 4];
            }
            unsigned bf[8][2];
#pragma unroll
            for (int nt = 0; nt < 8; nt++) {
                const unsigned* p = W_s + (k + qid) * RS + wn + nt * 8 + grp;
                bf[nt][0] = p[0];
                bf[nt][1] = p[4 * RS];
            }
#pragma unroll
            for (int mt = 0; mt < 2; mt++)
#pragma unroll
                for (int nt = 0; nt < 8; nt++)
                    mma_tf32(acc2[mt][nt], af[mt], bf[nt]);
        }
        // epilogue: sigmoid + clip -> C (a)
#pragma unroll
        for (int mt = 0; mt < 2; mt++) {
#pragma unroll
            for (int nt = 0; nt < 8; nt++) {
                int row = wm + mt * 16 + grp;
                int col = wn + nt * 8 + 2 * qid;
                float b0 = bias[col], b1 = bias[col + 1];
                float v0 = 1.0f / (1.0f + __expf(-(acc2[mt][nt][0] + b0)));
                float v1 = 1.0f / (1.0f + __expf(-(acc2[mt][nt][1] + b1)));
                float v2 = 1.0f / (1.0f + __expf(-(acc2[mt][nt][2] + b0)));
                float v3 = 1.0f / (1.0f + __expf(-(acc2[mt][nt][3] + b1)));
                v0 = fminf(fmaxf(v0, 0.01f), 0.995f);
                v1 = fminf(fmaxf(v1, 0.01f), 0.995f);
                v2 = fminf(fmaxf(v2, 0.01f), 0.995f);
                v3 = fminf(fmaxf(v3, 0.01f), 0.995f);
                size_t g0 = (m0 + row) * (size_t)ldc + col;
                size_t g2 = (m0 + row + 8) * (size_t)ldc + col;
                *(float2*)(C + g0) = make_float2(v0, v1);
                *(float2*)(C + g2) = make_float2(v2, v3);
            }
        }
    } else {
        // standard epilogue
#pragma unroll
        for (int mt = 0; mt < 2; mt++) {
#pragma unroll
            for (int nt = 0; nt < 8; nt++) {
                int row = wm + mt * 16 + grp;
                int col = wn + nt * 8 + 2 * qid;
                size_t g0 = (m0 + row) * (size_t)ldc + n0 + col;
                size_t g2 = (m0 + row + 8) * (size_t)ldc + n0 + col;
                float v0 = acc[mt][nt][0], v1 = acc[mt][nt][1];
                float v2 = acc[mt][nt][2], v3 = acc[mt][nt][3];
                if (MODE == 3) {
                    float2 r0 = *(const float2*)(X + g0);
                    float2 r2 = *(const float2*)(X + g2);
                    v0 += r0.x; v1 += r0.y; v2 += r2.x; v3 += r2.y;
                }
                *(float2*)(C + g0) = make_float2(v0, v1);
                *(float2*)(C + g2) = make_float2(v2, v3);
            }
        }
    }
}

// -------- sequential normalized scan: depth-8 register prefetch --------
__device__ __forceinline__ float4 f4mul(float4 a, float4 b) {
    return make_float4(a.x*b.x, a.y*b.y, a.z*b.z, a.w*b.w);
}
__device__ __forceinline__ float4 f4fms(float4 p, float s, float4 u) {
    return make_float4(fmaf(p.x,s,u.x), fmaf(p.y,s,u.y), fmaf(p.z,s,u.z), fmaf(p.w,s,u.w));
}
__device__ __forceinline__ float4 f4sc(float4 a, float s) {
    return make_float4(a.x*s, a.y*s, a.z*s, a.w*s);
}
__device__ __forceinline__ float f4ssq(float4 a) {
    return fmaf(a.x,a.x, a.y*a.y) + fmaf(a.z,a.z, a.w*a.w);
}

__global__ void __launch_bounds__(32)
scan_kernel(const float* __restrict__ A, const float* __restrict__ U,
            float* __restrict__ S, float* __restrict__ cache) {
    const int lane = threadIdx.x & 31;
    const int b    = blockIdx.x * 2 + (lane >> 4);
    const int li   = lane & 15;
    const size_t base = ((size_t)b * TLEN) * RDIM + li * 8;
    const float4* Ap = (const float4*)(A + base);
    const float4* Up = (const float4*)(U + base);
    float4*       Sp = (float4*)(S + base);

    float4 w0 = Up[0], w1 = Up[1];          // w_0 = u_0
    // slot j holds (a_{t+1}, u_{t+1}) for step t, t ≡ j (mod 8)
    float4 qa[8][2], qu[8][2];
#pragma unroll
    for (int j = 0; j < 8; j++) {
        size_t o = (size_t)(j + 1) * 32;
        qa[j][0] = Ap[o]; qa[j][1] = Ap[o + 1];
        qu[j][0] = Up[o]; qu[j][1] = Up[o + 1];
    }

    for (int t = 0; t < TLEN; t += 8) {
#pragma unroll
        for (int j = 0; j < 8; j++) {
            const int tt = t + j;
            float4 p0 = f4mul(qa[j][0], w0);
            float4 p1 = f4mul(qa[j][1], w1);
            float q = f4ssq(w0) + f4ssq(w1);
            q += __shfl_xor_sync(0xffffffffu, q, 1);
            q += __shfl_xor_sync(0xffffffffu, q, 2);
            q += __shfl_xor_sync(0xffffffffu, q, 4);
            q += __shfl_xor_sync(0xffffffffu, q, 8);
            float inv = rsqrtf(fmaf(q, 1.0f / 128.0f, EPS_V));
            float4 s0 = f4sc(w0, inv);
            float4 s1 = f4sc(w1, inv);
            size_t so = (size_t)tt * 32;
            Sp[so]     = s0;
            Sp[so + 1] = s1;
            if (tt == TLEN - 1) {
                *(float4*)(cache + b * RDIM + li * 8)     = s0;
                *(float4*)(cache + b * RDIM + li * 8 + 4) = s1;
            }
            // w_{t+1} = (a .* w) * inv + u  (single FMA after rsqrt)
            w0 = f4fms(p0, inv, qu[j][0]);
            w1 = f4fms(p1, inv, qu[j][1]);
            // refill slot for step tt+8 (needs data index tt+9)
            if (tt + 9 < TLEN) {
                size_t o = (size_t)(tt + 9) * 32;
                qa[j][0] = Ap[o]; qa[j][1] = Ap[o + 1];
                qu[j][0] = Up[o]; qu[j][1] = Up[o + 1];
            }
        }
    }
}

extern "C" void kernel_launch(void* const* d_in, const int* in_sizes, int n_in,
                              void* d_out, int out_size) {
    const float* t_in = (const float*)d_in[0];
    const float* F_in = (const float*)d_in[1];
    const float* V_r  = (const float*)d_in[2];
    const float* V_b  = (const float*)d_in[3];
    const float* V_o  = (const float*)d_in[4];
    const float* W_l  = (const float*)d_in[5];
    const float* b_l  = (const float*)d_in[6];
    float* out = (float*)d_out;

    float *u, *a, *s;
    cudaGetSymbolAddress((void**)&u, g_u);
    cudaGetSymbolAddress((void**)&a, g_a);
    cudaGetSymbolAddress((void**)&s, g_s);

    cudaFuncSetAttribute(gk<0>, cudaFuncAttributeMaxDynamicSharedMemorySize, SMEM_BYTES_FUSED);
    cudaFuncSetAttribute(gk<1>, cudaFuncAttributeMaxDynamicSharedMemorySize, SMEM_BYTES_STD);
    cudaFuncSetAttribute(gk<3>, cudaFuncAttributeMaxDynamicSharedMemorySize, SMEM_BYTES_STD);

    dim3 blk(256);
    // a = clip(sigmoid((t @ V_r) @ W_lambda + b_lambda))   [r never leaves the CTA]
    gk<0><<<dim3(MROWS / BM, 1), blk, SMEM_BYTES_FUSED>>>(
        t_in, nullptr, V_r, W_l, b_l, nullptr, a, PDIM, PDIM, RDIM, RDIM);
    // u = (F .* t) @ V_b * scale
    gk<1><<<dim3(MROWS / BM, 1), blk, SMEM_BYTES_STD>>>(
        t_in, F_in, V_b, nullptr, nullptr, nullptr, u, PDIM, PDIM, RDIM, RDIM);
    // sequential normalized scan (+ writes new_cache at tail of d_out)
    scan_kernel<<<4, 32>>>(a, u, s, out + (size_t)MROWS * PDIM);
    // t_tilde = s @ V_o + t
    gk<3><<<dim3(MROWS / BM, PDIM / BN), blk, SMEM_BYTES_STD>>>(
        s, nullptr, V_o, nullptr, nullptr, t_in, out, RDIM, RDIM, PDIM, PDIM);
}